// round 10
// baseline (speedup 1.0000x reference)
#include <cuda_runtime.h>
#include <cstdint>

// ---------------------------------------------------------------------------
// QuaternionBatchNorm (training forward), DIM=4
//   pass 1: per-feature sums, 4-deep load batching (reversed chunk order)
//   pass 2: tiny per-feature linear algebra -> W = gamma_sym @ L^-1, b_eff
//   pass 3: out = W @ x + b_eff; __ldcs/__stcs + L2 read-prefetch 2 groups
//           ahead to batch DRAM reads and reduce read/write turnarounds
// ---------------------------------------------------------------------------

#define MAXF   2048
#define SPLITB 64
#define TPB    256
#define ROWS_APPLY 32
#define EPS_L1 1e-5f
#define EPS_L2 0.1f

// scratch (all fully overwritten every call -> graph-replay deterministic)
__device__ float  g_partials[(size_t)SPLITB * 14 * MAXF]; // [split][k][F]
__device__ float4 g_W[MAXF * 4];                          // per-feature 4x4 rows
__device__ float4 g_beff[MAXF];                           // per-feature bias

#define ACCUM(v)                                  \
    do {                                          \
        s0 += (v).x; s1 += (v).y;                 \
        s2 += (v).z; s3 += (v).w;                 \
        p00 = fmaf((v).x, (v).x, p00);            \
        p01 = fmaf((v).x, (v).y, p01);            \
        p02 = fmaf((v).x, (v).z, p02);            \
        p03 = fmaf((v).x, (v).w, p03);            \
        p11 = fmaf((v).y, (v).y, p11);            \
        p12 = fmaf((v).y, (v).z, p12);            \
        p13 = fmaf((v).y, (v).w, p13);            \
        p22 = fmaf((v).z, (v).z, p22);            \
        p23 = fmaf((v).z, (v).w, p23);            \
        p33 = fmaf((v).w, (v).w, p33);            \
    } while (0)

// ---------------------------------------------------------------------------
// Kernel 1: partial sums. Thread owns feature f; coalesced float4 stream.
// ---------------------------------------------------------------------------
__global__ void qbn_stats(const float4* __restrict__ x, int B, int F) {
    int f  = blockIdx.x * blockDim.x + threadIdx.x;
    if (f >= F) return;
    int chunk = (int)gridDim.y - 1 - (int)blockIdx.y;  // reversed mapping
    int rows = (B + SPLITB - 1) / SPLITB;
    int b0   = chunk * rows;
    int nb   = min(rows, B - b0);

    float s0 = 0.f, s1 = 0.f, s2 = 0.f, s3 = 0.f;
    float p00 = 0.f, p01 = 0.f, p02 = 0.f, p03 = 0.f;
    float p11 = 0.f, p12 = 0.f, p13 = 0.f;
    float p22 = 0.f, p23 = 0.f, p33 = 0.f;

    const float4* xp = x + (size_t)b0 * F + f;
    int i = 0;
    #pragma unroll 2
    for (; i + 4 <= nb; i += 4) {
        float4 v0 = xp[(size_t)(i + 0) * F];
        float4 v1 = xp[(size_t)(i + 1) * F];
        float4 v2 = xp[(size_t)(i + 2) * F];
        float4 v3 = xp[(size_t)(i + 3) * F];
        ACCUM(v0); ACCUM(v1); ACCUM(v2); ACCUM(v3);
    }
    for (; i < nb; i++) {
        float4 v = xp[(size_t)i * F];
        ACCUM(v);
    }

    float* p = g_partials + ((size_t)blockIdx.y * 14) * F + f;
    p[0 * (size_t)F]  = s0;  p[1 * (size_t)F]  = s1;
    p[2 * (size_t)F]  = s2;  p[3 * (size_t)F]  = s3;
    p[4 * (size_t)F]  = p00; p[5 * (size_t)F]  = p01;
    p[6 * (size_t)F]  = p02; p[7 * (size_t)F]  = p03;
    p[8 * (size_t)F]  = p11; p[9 * (size_t)F]  = p12;
    p[10 * (size_t)F] = p13; p[11 * (size_t)F] = p22;
    p[12 * (size_t)F] = p23; p[13 * (size_t)F] = p33;
}

// ---------------------------------------------------------------------------
// 4x4 lower Cholesky; true iff all leading minors positive (LAPACK success).
// ---------------------------------------------------------------------------
__device__ __forceinline__ bool chol4(
    float a00, float a01, float a02, float a03,
    float a11, float a12, float a13,
    float a22, float a23, float a33, float L[10])
{
    bool ok = true;
    float d0 = a00;                      ok &= (d0 > 0.f);
    float l00 = sqrtf(d0);
    float i0  = 1.f / l00;
    float l10 = a01 * i0, l20 = a02 * i0, l30 = a03 * i0;
    float d1 = a11 - l10 * l10;          ok &= (d1 > 0.f);
    float l11 = sqrtf(d1);
    float i1  = 1.f / l11;
    float l21 = (a12 - l20 * l10) * i1;
    float l31 = (a13 - l30 * l10) * i1;
    float d2 = a22 - l20 * l20 - l21 * l21;  ok &= (d2 > 0.f);
    float l22 = sqrtf(d2);
    float i2  = 1.f / l22;
    float l32 = (a23 - l30 * l20 - l31 * l21) * i2;
    float d3 = a33 - l30 * l30 - l31 * l31 - l32 * l32; ok &= (d3 > 0.f);
    float l33 = sqrtf(d3);
    L[0] = l00; L[1] = l10; L[2] = l11; L[3] = l20; L[4] = l21;
    L[5] = l22; L[6] = l30; L[7] = l31; L[8] = l32; L[9] = l33;
    return ok;
}

// ---------------------------------------------------------------------------
// Kernel 2: per-feature finalize -> W, b_eff
// ---------------------------------------------------------------------------
__global__ void qbn_finalize(const float* __restrict__ gamma,
                             const float* __restrict__ beta,
                             int B, int F) {
    int f = blockIdx.x * blockDim.x + threadIdx.x;
    if (f >= F) return;

    float acc[14];
    #pragma unroll
    for (int k = 0; k < 14; k++) acc[k] = 0.f;
    for (int sb = 0; sb < SPLITB; sb++) {
        const float* p = g_partials + ((size_t)sb * 14) * F + f;
        #pragma unroll
        for (int k = 0; k < 14; k++) acc[k] += p[(size_t)k * F];
    }

    float invB = 1.0f / (float)B;
    float m0 = acc[0] * invB, m1 = acc[1] * invB;
    float m2 = acc[2] * invB, m3 = acc[3] * invB;
    float c00 = acc[4]  * invB - m0 * m0;
    float c01 = acc[5]  * invB - m0 * m1;
    float c02 = acc[6]  * invB - m0 * m2;
    float c03 = acc[7]  * invB - m0 * m3;
    float c11 = acc[8]  * invB - m1 * m1;
    float c12 = acc[9]  * invB - m1 * m2;
    float c13 = acc[10] * invB - m1 * m3;
    float c22 = acc[11] * invB - m2 * m2;
    float c23 = acc[12] * invB - m2 * m3;
    float c33 = acc[13] * invB - m3 * m3;

    // 3-level fallback Cholesky (matches reference semantics)
    float L[10];
    bool ok1 = chol4(c00 + EPS_L1, c01, c02, c03,
                     c11 + EPS_L1, c12, c13,
                     c22 + EPS_L1, c23, c33 + EPS_L1, L);
    if (!ok1) {
        float L2a[10];
        bool ok2 = chol4(c00 + EPS_L2, c01, c02, c03,
                         c11 + EPS_L2, c12, c13,
                         c22 + EPS_L2, c23, c33 + EPS_L2, L2a);
        if (ok2) {
            #pragma unroll
            for (int k = 0; k < 10; k++) L[k] = L2a[k];
        } else {
            float dm = 0.25f * (fabsf(c00) + fabsf(c11) + fabsf(c22) + fabsf(c33));
            float sc = sqrtf(fmaxf(dm, 1.0f));
            L[0] = sc; L[1] = 0.f; L[2] = sc; L[3] = 0.f; L[4] = 0.f;
            L[5] = sc; L[6] = 0.f; L[7] = 0.f; L[8] = 0.f; L[9] = sc;
        }
    }

    // L^{-1} by forward substitution (lower triangular)
    float i00 = 1.f / L[0];
    float i11 = 1.f / L[2];
    float i22 = 1.f / L[5];
    float i33 = 1.f / L[9];
    float i10 = -L[1] * i00 * i11;
    float i20 = -(L[3] * i00 + L[4] * i10) * i22;
    float i21 = -L[4] * i11 * i22;
    float i30 = -(L[6] * i00 + L[7] * i10 + L[8] * i20) * i33;
    float i31 = -(L[7] * i11 + L[8] * i21) * i33;
    float i32 = -L[8] * i22 * i33;

    float Li[4][4] = {
        { i00, 0.f, 0.f, 0.f },
        { i10, i11, 0.f, 0.f },
        { i20, i21, i22, 0.f },
        { i30, i31, i32, i33 }
    };

    // gamma symmetric from tril order:
    // (0,0)(1,0)(1,1)(2,0)(2,1)(2,2)(3,0)(3,1)(3,2)(3,3)
    const float* g = gamma + (size_t)f * 10;
    float g0 = g[0], g1 = g[1], g2 = g[2], g3 = g[3], g4 = g[4];
    float g5 = g[5], g6 = g[6], g7 = g[7], g8 = g[8], g9 = g[9];
    float G[4][4] = {
        { g0, g1, g3, g6 },
        { g1, g2, g4, g7 },
        { g3, g4, g5, g8 },
        { g6, g7, g8, g9 }
    };

    // W = G @ Li
    float W[4][4];
    #pragma unroll
    for (int i = 0; i < 4; i++)
        #pragma unroll
        for (int j = 0; j < 4; j++) {
            float s = 0.f;
            #pragma unroll
            for (int k = 0; k < 4; k++) s = fmaf(G[i][k], Li[k][j], s);
            W[i][j] = s;
        }

    // b_eff = beta - W @ mean
    const float* bt = beta + (size_t)f * 4;
    float mvec[4] = { m0, m1, m2, m3 };
    float be[4];
    #pragma unroll
    for (int i = 0; i < 4; i++) {
        float s = bt[i];
        #pragma unroll
        for (int j = 0; j < 4; j++) s = fmaf(-W[i][j], mvec[j], s);
        be[i] = s;
    }

    #pragma unroll
    for (int i = 0; i < 4; i++)
        g_W[f * 4 + i] = make_float4(W[i][0], W[i][1], W[i][2], W[i][3]);
    g_beff[f] = make_float4(be[0], be[1], be[2], be[3]);
}

// ---------------------------------------------------------------------------
// Kernel 3: out = W @ x + b_eff. Thread owns feature f; table in registers.
// 4-deep batch; L2 prefetch two groups ahead (one lane per 128B line).
// ---------------------------------------------------------------------------
__device__ __forceinline__ float4 qbn_mv(float4 w0, float4 w1, float4 w2,
                                         float4 w3, float4 bb, float4 v) {
    float4 r;
    r.x = fmaf(w0.x, v.x, fmaf(w0.y, v.y, fmaf(w0.z, v.z, fmaf(w0.w, v.w, bb.x))));
    r.y = fmaf(w1.x, v.x, fmaf(w1.y, v.y, fmaf(w1.z, v.z, fmaf(w1.w, v.w, bb.y))));
    r.z = fmaf(w2.x, v.x, fmaf(w2.y, v.y, fmaf(w2.z, v.z, fmaf(w2.w, v.w, bb.z))));
    r.w = fmaf(w3.x, v.x, fmaf(w3.y, v.y, fmaf(w3.z, v.z, fmaf(w3.w, v.w, bb.w))));
    return r;
}

__global__ void __launch_bounds__(TPB)
qbn_apply(const float4* __restrict__ x, float4* __restrict__ out,
          int B, int F) {
    int f  = blockIdx.x * blockDim.x + threadIdx.x;
    if (f >= F) return;
    int b0 = blockIdx.y * ROWS_APPLY;
    int nb = min(ROWS_APPLY, B - b0);
    bool pfl = (threadIdx.x & 7) == 0;    // one lane per 128B line

    float4 w0 = g_W[f * 4 + 0];
    float4 w1 = g_W[f * 4 + 1];
    float4 w2 = g_W[f * 4 + 2];
    float4 w3 = g_W[f * 4 + 3];
    float4 bb = g_beff[f];

    const float4* xp = x   + (size_t)b0 * F + f;
    float4*       op = out + (size_t)b0 * F + f;

    int i = 0;
    #pragma unroll 2
    for (; i + 4 <= nb; i += 4) {
        // prefetch the group two iterations ahead into L2 (reads batched
        // ahead of the store stream; rows clamped to stay in-bounds)
        if (pfl) {
            int pr = min(b0 + i + 8, B - 4);
            const float4* pp = x + (size_t)pr * F + f;
            asm volatile("prefetch.global.L2 [%0];" :: "l"(pp + 0 * (size_t)F));
            asm volatile("prefetch.global.L2 [%0];" :: "l"(pp + 1 * (size_t)F));
            asm volatile("prefetch.global.L2 [%0];" :: "l"(pp + 2 * (size_t)F));
            asm volatile("prefetch.global.L2 [%0];" :: "l"(pp + 3 * (size_t)F));
        }
        float4 v0 = __ldcs(&xp[(size_t)(i + 0) * F]);
        float4 v1 = __ldcs(&xp[(size_t)(i + 1) * F]);
        float4 v2 = __ldcs(&xp[(size_t)(i + 2) * F]);
        float4 v3 = __ldcs(&xp[(size_t)(i + 3) * F]);
        __stcs(&op[(size_t)(i + 0) * F], qbn_mv(w0, w1, w2, w3, bb, v0));
        __stcs(&op[(size_t)(i + 1) * F], qbn_mv(w0, w1, w2, w3, bb, v1));
        __stcs(&op[(size_t)(i + 2) * F], qbn_mv(w0, w1, w2, w3, bb, v2));
        __stcs(&op[(size_t)(i + 3) * F], qbn_mv(w0, w1, w2, w3, bb, v3));
    }
    for (; i < nb; i++) {
        float4 v = __ldcs(&xp[(size_t)i * F]);
        __stcs(&op[(size_t)i * F], qbn_mv(w0, w1, w2, w3, bb, v));
    }
}

// ---------------------------------------------------------------------------
extern "C" void kernel_launch(void* const* d_in, const int* in_sizes, int n_in,
                              void* d_out, int out_size) {
    const float* x     = (const float*)d_in[0];
    const float* gamma = (const float*)d_in[1];
    const float* beta  = (const float*)d_in[2];
    float*       out   = (float*)d_out;

    int F = in_sizes[2] / 4;            // beta is [F,4]
    int B = in_sizes[0] / (F * 4);      // x is [B,F,4]

    dim3 g1((F + TPB - 1) / TPB, SPLITB);
    qbn_stats<<<g1, TPB>>>((const float4*)x, B, F);

    qbn_finalize<<<(F + 127) / 128, 128>>>(gamma, beta, B, F);

    dim3 g3((F + TPB - 1) / TPB, (B + ROWS_APPLY - 1) / ROWS_APPLY);
    qbn_apply<<<g3, TPB>>>((const float4*)x, (float4*)out, B, F);
}

// round 11
// speedup vs baseline: 1.2078x; 1.2078x over previous
#include <cuda_runtime.h>
#include <cstdint>

// ---------------------------------------------------------------------------
// QuaternionBatchNorm (training forward), DIM=4
//   pass 1: per-feature sums, 4-deep load batching (reversed chunk order)
//   pass 2: finalize with PARALLEL split-reduction (32 feat x 8 lanes / CTA)
//   pass 3: out = W @ x + b_eff; __ldcs/__stcs, 4-deep batch  (R5 verbatim)
// ---------------------------------------------------------------------------

#define MAXF   2048
#define SPLITB 64
#define TPB    256
#define ROWS_APPLY 32
#define EPS_L1 1e-5f
#define EPS_L2 0.1f

// finalize geometry: 256 threads = 32 features x 8 split-lanes
#define FIN_F   32
#define FIN_L   8
#define FIN_SPL (SPLITB / FIN_L)   // 8 splits summed serially per lane

// scratch (all fully overwritten every call -> graph-replay deterministic)
__device__ float  g_partials[(size_t)SPLITB * 14 * MAXF]; // [split][k][F]
__device__ float4 g_W[MAXF * 4];                          // per-feature 4x4 rows
__device__ float4 g_beff[MAXF];                           // per-feature bias

#define ACCUM(v)                                  \
    do {                                          \
        s0 += (v).x; s1 += (v).y;                 \
        s2 += (v).z; s3 += (v).w;                 \
        p00 = fmaf((v).x, (v).x, p00);            \
        p01 = fmaf((v).x, (v).y, p01);            \
        p02 = fmaf((v).x, (v).z, p02);            \
        p03 = fmaf((v).x, (v).w, p03);            \
        p11 = fmaf((v).y, (v).y, p11);            \
        p12 = fmaf((v).y, (v).z, p12);            \
        p13 = fmaf((v).y, (v).w, p13);            \
        p22 = fmaf((v).z, (v).z, p22);            \
        p23 = fmaf((v).z, (v).w, p23);            \
        p33 = fmaf((v).w, (v).w, p33);            \
    } while (0)

// ---------------------------------------------------------------------------
// Kernel 1: partial sums. Thread owns feature f; coalesced float4 stream.
// ---------------------------------------------------------------------------
__global__ void qbn_stats(const float4* __restrict__ x, int B, int F) {
    int f  = blockIdx.x * blockDim.x + threadIdx.x;
    if (f >= F) return;
    int chunk = (int)gridDim.y - 1 - (int)blockIdx.y;  // reversed mapping
    int rows = (B + SPLITB - 1) / SPLITB;
    int b0   = chunk * rows;
    int nb   = min(rows, B - b0);

    float s0 = 0.f, s1 = 0.f, s2 = 0.f, s3 = 0.f;
    float p00 = 0.f, p01 = 0.f, p02 = 0.f, p03 = 0.f;
    float p11 = 0.f, p12 = 0.f, p13 = 0.f;
    float p22 = 0.f, p23 = 0.f, p33 = 0.f;

    const float4* xp = x + (size_t)b0 * F + f;
    int i = 0;
    #pragma unroll 2
    for (; i + 4 <= nb; i += 4) {
        float4 v0 = xp[(size_t)(i + 0) * F];
        float4 v1 = xp[(size_t)(i + 1) * F];
        float4 v2 = xp[(size_t)(i + 2) * F];
        float4 v3 = xp[(size_t)(i + 3) * F];
        ACCUM(v0); ACCUM(v1); ACCUM(v2); ACCUM(v3);
    }
    for (; i < nb; i++) {
        float4 v = xp[(size_t)i * F];
        ACCUM(v);
    }

    float* p = g_partials + ((size_t)blockIdx.y * 14) * F + f;
    p[0 * (size_t)F]  = s0;  p[1 * (size_t)F]  = s1;
    p[2 * (size_t)F]  = s2;  p[3 * (size_t)F]  = s3;
    p[4 * (size_t)F]  = p00; p[5 * (size_t)F]  = p01;
    p[6 * (size_t)F]  = p02; p[7 * (size_t)F]  = p03;
    p[8 * (size_t)F]  = p11; p[9 * (size_t)F]  = p12;
    p[10 * (size_t)F] = p13; p[11 * (size_t)F] = p22;
    p[12 * (size_t)F] = p23; p[13 * (size_t)F] = p33;
}

// ---------------------------------------------------------------------------
// 4x4 lower Cholesky; true iff all leading minors positive (LAPACK success).
// ---------------------------------------------------------------------------
__device__ __forceinline__ bool chol4(
    float a00, float a01, float a02, float a03,
    float a11, float a12, float a13,
    float a22, float a23, float a33, float L[10])
{
    bool ok = true;
    float d0 = a00;                      ok &= (d0 > 0.f);
    float l00 = sqrtf(d0);
    float i0  = 1.f / l00;
    float l10 = a01 * i0, l20 = a02 * i0, l30 = a03 * i0;
    float d1 = a11 - l10 * l10;          ok &= (d1 > 0.f);
    float l11 = sqrtf(d1);
    float i1  = 1.f / l11;
    float l21 = (a12 - l20 * l10) * i1;
    float l31 = (a13 - l30 * l10) * i1;
    float d2 = a22 - l20 * l20 - l21 * l21;  ok &= (d2 > 0.f);
    float l22 = sqrtf(d2);
    float i2  = 1.f / l22;
    float l32 = (a23 - l30 * l20 - l31 * l21) * i2;
    float d3 = a33 - l30 * l30 - l31 * l31 - l32 * l32; ok &= (d3 > 0.f);
    float l33 = sqrtf(d3);
    L[0] = l00; L[1] = l10; L[2] = l11; L[3] = l20; L[4] = l21;
    L[5] = l22; L[6] = l30; L[7] = l31; L[8] = l32; L[9] = l33;
    return ok;
}

// ---------------------------------------------------------------------------
// Kernel 2: finalize with parallel split-reduction.
// Block = 256 threads = 32 features x 8 lanes. Each lane serially sums 8
// splits; SMEM tree folds lanes 8 -> 1; lane 0 does Cholesky + fold.
// ---------------------------------------------------------------------------
__global__ void __launch_bounds__(FIN_F * FIN_L)
qbn_finalize(const float* __restrict__ gamma,
             const float* __restrict__ beta,
             int B, int F) {
    __shared__ float red[FIN_L][14][FIN_F];   // [lane][k][f_local], 14 KB

    int tid  = threadIdx.x;
    int fl   = tid % FIN_F;        // feature within block (coalesced axis)
    int lane = tid / FIN_F;        // split-lane 0..7
    int f    = blockIdx.x * FIN_F + fl;
    bool valid = (f < F);

    float acc[14];
    #pragma unroll
    for (int k = 0; k < 14; k++) acc[k] = 0.f;

    if (valid) {
        int sb0 = lane * FIN_SPL;
        for (int s = 0; s < FIN_SPL; s++) {
            const float* p = g_partials + ((size_t)(sb0 + s) * 14) * F + f;
            #pragma unroll
            for (int k = 0; k < 14; k++) acc[k] += p[(size_t)k * F];
        }
    }
    #pragma unroll
    for (int k = 0; k < 14; k++) red[lane][k][fl] = acc[k];
    __syncthreads();

    // tree fold 8 lanes -> 1
    #pragma unroll
    for (int s = FIN_L / 2; s >= 1; s >>= 1) {
        if (lane < s) {
            #pragma unroll
            for (int k = 0; k < 14; k++)
                red[lane][k][fl] += red[lane + s][k][fl];
        }
        __syncthreads();
    }

    if (lane != 0 || !valid) return;
    #pragma unroll
    for (int k = 0; k < 14; k++) acc[k] = red[0][k][fl];

    float invB = 1.0f / (float)B;
    float m0 = acc[0] * invB, m1 = acc[1] * invB;
    float m2 = acc[2] * invB, m3 = acc[3] * invB;
    float c00 = acc[4]  * invB - m0 * m0;
    float c01 = acc[5]  * invB - m0 * m1;
    float c02 = acc[6]  * invB - m0 * m2;
    float c03 = acc[7]  * invB - m0 * m3;
    float c11 = acc[8]  * invB - m1 * m1;
    float c12 = acc[9]  * invB - m1 * m2;
    float c13 = acc[10] * invB - m1 * m3;
    float c22 = acc[11] * invB - m2 * m2;
    float c23 = acc[12] * invB - m2 * m3;
    float c33 = acc[13] * invB - m3 * m3;

    // 3-level fallback Cholesky (matches reference semantics)
    float L[10];
    bool ok1 = chol4(c00 + EPS_L1, c01, c02, c03,
                     c11 + EPS_L1, c12, c13,
                     c22 + EPS_L1, c23, c33 + EPS_L1, L);
    if (!ok1) {
        float L2a[10];
        bool ok2 = chol4(c00 + EPS_L2, c01, c02, c03,
                         c11 + EPS_L2, c12, c13,
                         c22 + EPS_L2, c23, c33 + EPS_L2, L2a);
        if (ok2) {
            #pragma unroll
            for (int k = 0; k < 10; k++) L[k] = L2a[k];
        } else {
            float dm = 0.25f * (fabsf(c00) + fabsf(c11) + fabsf(c22) + fabsf(c33));
            float sc = sqrtf(fmaxf(dm, 1.0f));
            L[0] = sc; L[1] = 0.f; L[2] = sc; L[3] = 0.f; L[4] = 0.f;
            L[5] = sc; L[6] = 0.f; L[7] = 0.f; L[8] = 0.f; L[9] = sc;
        }
    }

    // L^{-1} by forward substitution (lower triangular)
    float i00 = 1.f / L[0];
    float i11 = 1.f / L[2];
    float i22 = 1.f / L[5];
    float i33 = 1.f / L[9];
    float i10 = -L[1] * i00 * i11;
    float i20 = -(L[3] * i00 + L[4] * i10) * i22;
    float i21 = -L[4] * i11 * i22;
    float i30 = -(L[6] * i00 + L[7] * i10 + L[8] * i20) * i33;
    float i31 = -(L[7] * i11 + L[8] * i21) * i33;
    float i32 = -L[8] * i22 * i33;

    float Li[4][4] = {
        { i00, 0.f, 0.f, 0.f },
        { i10, i11, 0.f, 0.f },
        { i20, i21, i22, 0.f },
        { i30, i31, i32, i33 }
    };

    // gamma symmetric from tril order:
    // (0,0)(1,0)(1,1)(2,0)(2,1)(2,2)(3,0)(3,1)(3,2)(3,3)
    const float* g = gamma + (size_t)f * 10;
    float g0 = g[0], g1 = g[1], g2 = g[2], g3 = g[3], g4 = g[4];
    float g5 = g[5], g6 = g[6], g7 = g[7], g8 = g[8], g9 = g[9];
    float G[4][4] = {
        { g0, g1, g3, g6 },
        { g1, g2, g4, g7 },
        { g3, g4, g5, g8 },
        { g6, g7, g8, g9 }
    };

    // W = G @ Li
    float W[4][4];
    #pragma unroll
    for (int i = 0; i < 4; i++)
        #pragma unroll
        for (int j = 0; j < 4; j++) {
            float s = 0.f;
            #pragma unroll
            for (int k = 0; k < 4; k++) s = fmaf(G[i][k], Li[k][j], s);
            W[i][j] = s;
        }

    // b_eff = beta - W @ mean
    const float* bt = beta + (size_t)f * 4;
    float mvec[4] = { m0, m1, m2, m3 };
    float be[4];
    #pragma unroll
    for (int i = 0; i < 4; i++) {
        float s = bt[i];
        #pragma unroll
        for (int j = 0; j < 4; j++) s = fmaf(-W[i][j], mvec[j], s);
        be[i] = s;
    }

    #pragma unroll
    for (int i = 0; i < 4; i++)
        g_W[f * 4 + i] = make_float4(W[i][0], W[i][1], W[i][2], W[i][3]);
    g_beff[f] = make_float4(be[0], be[1], be[2], be[3]);
}

// ---------------------------------------------------------------------------
// Kernel 3: out = W @ x + b_eff. Thread owns feature f; table in registers.
// 4-deep batch; streaming cache hints (read-once x, write-once out).
// ---------------------------------------------------------------------------
__device__ __forceinline__ float4 qbn_mv(float4 w0, float4 w1, float4 w2,
                                         float4 w3, float4 bb, float4 v) {
    float4 r;
    r.x = fmaf(w0.x, v.x, fmaf(w0.y, v.y, fmaf(w0.z, v.z, fmaf(w0.w, v.w, bb.x))));
    r.y = fmaf(w1.x, v.x, fmaf(w1.y, v.y, fmaf(w1.z, v.z, fmaf(w1.w, v.w, bb.y))));
    r.z = fmaf(w2.x, v.x, fmaf(w2.y, v.y, fmaf(w2.z, v.z, fmaf(w2.w, v.w, bb.z))));
    r.w = fmaf(w3.x, v.x, fmaf(w3.y, v.y, fmaf(w3.z, v.z, fmaf(w3.w, v.w, bb.w))));
    return r;
}

__global__ void __launch_bounds__(TPB)
qbn_apply(const float4* __restrict__ x, float4* __restrict__ out,
          int B, int F) {
    int f  = blockIdx.x * blockDim.x + threadIdx.x;
    if (f >= F) return;
    int b0 = blockIdx.y * ROWS_APPLY;
    int nb = min(ROWS_APPLY, B - b0);

    float4 w0 = g_W[f * 4 + 0];
    float4 w1 = g_W[f * 4 + 1];
    float4 w2 = g_W[f * 4 + 2];
    float4 w3 = g_W[f * 4 + 3];
    float4 bb = g_beff[f];

    const float4* xp = x   + (size_t)b0 * F + f;
    float4*       op = out + (size_t)b0 * F + f;

    int i = 0;
    #pragma unroll 2
    for (; i + 4 <= nb; i += 4) {
        float4 v0 = __ldcs(&xp[(size_t)(i + 0) * F]);
        float4 v1 = __ldcs(&xp[(size_t)(i + 1) * F]);
        float4 v2 = __ldcs(&xp[(size_t)(i + 2) * F]);
        float4 v3 = __ldcs(&xp[(size_t)(i + 3) * F]);
        __stcs(&op[(size_t)(i + 0) * F], qbn_mv(w0, w1, w2, w3, bb, v0));
        __stcs(&op[(size_t)(i + 1) * F], qbn_mv(w0, w1, w2, w3, bb, v1));
        __stcs(&op[(size_t)(i + 2) * F], qbn_mv(w0, w1, w2, w3, bb, v2));
        __stcs(&op[(size_t)(i + 3) * F], qbn_mv(w0, w1, w2, w3, bb, v3));
    }
    for (; i < nb; i++) {
        float4 v = __ldcs(&xp[(size_t)i * F]);
        __stcs(&op[(size_t)i * F], qbn_mv(w0, w1, w2, w3, bb, v));
    }
}

// ---------------------------------------------------------------------------
extern "C" void kernel_launch(void* const* d_in, const int* in_sizes, int n_in,
                              void* d_out, int out_size) {
    const float* x     = (const float*)d_in[0];
    const float* gamma = (const float*)d_in[1];
    const float* beta  = (const float*)d_in[2];
    float*       out   = (float*)d_out;

    int F = in_sizes[2] / 4;            // beta is [F,4]
    int B = in_sizes[0] / (F * 4);      // x is [B,F,4]

    dim3 g1((F + TPB - 1) / TPB, SPLITB);
    qbn_stats<<<g1, TPB>>>((const float4*)x, B, F);

    qbn_finalize<<<(F + FIN_F - 1) / FIN_F, FIN_F * FIN_L>>>(gamma, beta, B, F);

    dim3 g3((F + TPB - 1) / TPB, (B + ROWS_APPLY - 1) / ROWS_APPLY);
    qbn_apply<<<g3, TPB>>>((const float4*)x, (float4*)out, B, F);
}